// round 11
// baseline (speedup 1.0000x reference)
#include <cuda_runtime.h>
#include <cstdint>
#include <cstddef>

#define Bn 256
#define Ln 1024
#define Vn 40
#define Hn 128

// ---- packed f32x2 helpers (FFMA2 only reachable via PTX) ----
__device__ __forceinline__ unsigned long long ffma2(unsigned long long a,
                                                    unsigned long long b,
                                                    unsigned long long c) {
    unsigned long long d;
    asm("fma.rn.f32x2 %0, %1, %2, %3;" : "=l"(d) : "l"(a), "l"(b), "l"(c));
    return d;
}
__device__ __forceinline__ unsigned long long add2(unsigned long long a,
                                                   unsigned long long b) {
    unsigned long long d;
    asm("add.rn.f32x2 %0, %1, %2;" : "=l"(d) : "l"(a), "l"(b));
    return d;
}
__device__ __forceinline__ float plo(unsigned long long a) {
    return __int_as_float((int)(unsigned)(a & 0xffffffffull));
}
__device__ __forceinline__ float phi(unsigned long long a) {
    return __int_as_float((int)(unsigned)(a >> 32));
}
__device__ __forceinline__ float tanh_fast(float x) {
    float r;
    asm("tanh.approx.f32 %0, %1;" : "=f"(r) : "f"(x));
    return r;
}
__device__ __forceinline__ void bar_named(int id, int cnt) {
    asm volatile("bar.sync %0, %1;" :: "r"(id), "r"(cnt) : "memory");
}

// =====================================================================
// Fused CharRNN, pairwise-barrier version (R7 dataflow + named bars).
// Thread t: e0 = t&63, kh = t>>6. Computes half-k partials for h elems
// e0, e0+64 and logit v=e0 (zero-padded v>=40); 96 FFMA2, 16 LDS.128.
//
// Sync graph per step (NO full-CTA barrier):
//   BAR_X (exchange, partner t^64):  pairs {w0,w2} id1, {w1,w3} id2
//   BAR_H (h publish, same k-half):  pairs {w0,w1} id3, {w2,w3} id4
// kh0 threads read only h[0..63] (written by t<64) and vice versa, so
// BAR_H legitimately splits. Exchange buffers are double-buffered to
// close the WAR window opened by decoupled pair progress. Exchange
// arrays are scalar (stride-1, conflict-free) instead of float4
// (old read had a 4-way bank conflict).
// Logit timing: iter l emits row l-1; row Ln-1 in an epilogue.
// =====================================================================
__global__ void __launch_bounds__(128, 2) fused_rnn_kernel(
    const int* __restrict__ x, const float* __restrict__ h0,
    const float* __restrict__ emb, const float* __restrict__ Wh,
    const float* __restrict__ Wo, const float* __restrict__ bh,
    const float* __restrict__ by, float* __restrict__ out,
    float* __restrict__ final_h)
{
    __shared__ __align__(16) float s_emb[Vn * Hn];   // 20 KB
    __shared__ int s_x[Ln];                          // 4 KB
    __shared__ __align__(16) float s_h[2][Hn];       // ping-pong h
    __shared__ float sp0[2][Hn];                     // partial of elem e0
    __shared__ float sp1[2][Hn];                     // partial of elem e0+64
    __shared__ float slp[2][Hn];                     // logit partial

    const int t   = threadIdx.x;
    const int b   = blockIdx.x;
    const int e0  = t & 63;
    const int kh  = t >> 6;                          // warp-uniform
    const int wid = t >> 5;
    const int idX = 1 + (wid & 1);                   // exchange pair barrier
    const int idH = 3 + (wid >> 1);                  // h-publish pair barrier

    for (int i = t; i < Vn * Hn; i += 128) s_emb[i] = emb[i];
    for (int i = t; i < Ln; i += 128) s_x[i] = x[b * Ln + i];
    s_h[0][t] = h0[b * Hn + t];
    const float bh0 = bh[e0];
    const float bh1 = bh[e0 + 64];
    const bool  dv  = (e0 < Vn);
    const float byv = dv ? by[e0] : 0.f;

    // wh[0..31]: Wh row e0, cols [64kh,64kh+64); wh[32..63]: row e0+64
    unsigned long long wh[64];
    {
        const ulonglong2* w0 = (const ulonglong2*)(Wh + e0 * Hn + kh * 64);
        const ulonglong2* w1 = (const ulonglong2*)(Wh + (e0 + 64) * Hn + kh * 64);
#pragma unroll
        for (int i = 0; i < 16; i++) {
            ulonglong2 p = w0[i];
            wh[2 * i] = p.x; wh[2 * i + 1] = p.y;
        }
#pragma unroll
        for (int i = 0; i < 16; i++) {
            ulonglong2 p = w1[i];
            wh[32 + 2 * i] = p.x; wh[33 + 2 * i] = p.y;
        }
    }
    // wo[0..31]: Wo row v=e0, cols [64kh,64kh+64) (zeros if v >= 40)
    unsigned long long wo[32];
    if (dv) {
        const ulonglong2* wv = (const ulonglong2*)(Wo + e0 * Hn + kh * 64);
#pragma unroll
        for (int i = 0; i < 16; i++) {
            ulonglong2 p = wv[i];
            wo[2 * i] = p.x; wo[2 * i + 1] = p.y;
        }
    } else {
#pragma unroll
        for (int i = 0; i < 32; i++) wo[i] = 0ull;
    }
    __syncthreads();

    float* obase = out + (size_t)b * Ln * Vn;

    // Prefetch embedding terms for step 0 (kh=0 warps; warp-uniform)
    float em0c = 0.f, em1c = 0.f;
    if (kh == 0) {
        const int idx0 = s_x[0];
        em0c = s_emb[idx0 * Hn + e0];
        em1c = s_emb[idx0 * Hn + e0 + 64];
    }

#pragma unroll 1
    for (int l = 0; l < Ln; l++) {
        const int buf = l & 1;
        // h entering step l == output of step l-1 (LDS.128 broadcast)
        const ulonglong2* hp = (const ulonglong2*)(s_h[buf]) + kh * 16;

        unsigned long long a0 = 0, a1 = 0;   // h elem e0
        unsigned long long c0 = 0, c1 = 0;   // h elem e0+64
        unsigned long long g0 = 0, g1 = 0;   // logit v=e0 (for row l-1)
#pragma unroll
        for (int i = 0; i < 16; i++) {
            ulonglong2 p = hp[i];            // LDS.128 -> feeds 6 FFMA2
            a0 = ffma2(wh[2 * i],      p.x, a0);
            c0 = ffma2(wh[32 + 2 * i], p.x, c0);
            g0 = ffma2(wo[2 * i],      p.x, g0);
            a1 = ffma2(wh[2 * i + 1],  p.y, a1);
            c1 = ffma2(wh[33 + 2 * i], p.y, c1);
            g1 = ffma2(wo[2 * i + 1],  p.y, g1);
        }
        a0 = add2(a0, a1);
        c0 = add2(c0, c1);
        g0 = add2(g0, g1);
        float pe0 = plo(a0) + phi(a0);
        float pe1 = plo(c0) + phi(c0);
        const float lp = plo(g0) + phi(g0);

        if (kh == 0) {                        // fold em + bh exactly once
            pe0 += em0c + bh0;
            pe1 += em1c + bh1;
        }
        sp0[buf][t] = pe0;                    // stride-1, conflict-free
        sp1[buf][t] = pe1;
        slp[buf][t] = lp;

        // Register-prefetch embedding for step l+1 (hidden by barrier)
        if (kh == 0) {
            const int idxn = s_x[(l + 1) & (Ln - 1)];
            em0c = s_emb[idxn * Hn + e0];
            em1c = s_emb[idxn * Hn + e0 + 64];
        }
        bar_named(idX, 64);                   // exchange pair {t, t^64}

        // Every thread finalizes elem t (conflict-free stride-1 reads)
        float hn;
        if (kh == 0) {
            hn = tanh_fast(pe0 + sp0[buf][t + 64]);
        } else {
            hn = tanh_fast(pe1 + sp1[buf][t - 64]);
        }
        s_h[buf ^ 1][t] = hn;                 // coalesced STS.32

        if (kh == 0 && dv && l > 0) {         // logit row l-1
            obase[(size_t)(l - 1) * Vn + e0] = lp + slp[buf][t + 64] + byv;
        }
        bar_named(idH, 64);                   // h-publish pair (same k-half)
    }

    __syncthreads();

    // Epilogue: logit row Ln-1 from the final hidden state (s_h[0]).
    {
        const ulonglong2* hp = (const ulonglong2*)(s_h[0]) + kh * 16;
        unsigned long long g0 = 0, g1 = 0;
#pragma unroll
        for (int i = 0; i < 16; i++) {
            ulonglong2 p = hp[i];
            g0 = ffma2(wo[2 * i],     p.x, g0);
            g1 = ffma2(wo[2 * i + 1], p.y, g1);
        }
        g0 = add2(g0, g1);
        const float lp = plo(g0) + phi(g0);
        slp[0][t] = lp;
        __syncthreads();
        if (kh == 0 && dv) {
            obase[(size_t)(Ln - 1) * Vn + e0] = lp + slp[0][t + 64] + byv;
        }
    }

    final_h[b * Hn + t] = s_h[0][t];   // Ln even -> final state in buffer 0
}

extern "C" void kernel_launch(void* const* d_in, const int* in_sizes, int n_in,
                              void* d_out, int out_size)
{
    const int*   x   = (const int*)d_in[0];
    const float* h0  = (const float*)d_in[1];
    const float* emb = (const float*)d_in[2];
    const float* Wh  = (const float*)d_in[3];
    const float* Wo  = (const float*)d_in[4];
    const float* bh  = (const float*)d_in[5];
    const float* by  = (const float*)d_in[6];

    float* out     = (float*)d_out;
    float* logits  = out;                               // [B, L, V]
    float* final_h = out + (size_t)Bn * Ln * Vn;        // [B, H]

    fused_rnn_kernel<<<Bn, 128>>>(x, h0, emb, Wh, Wo, bh, by, logits, final_h);
}